// round 15
// baseline (speedup 1.0000x reference)
#include <cuda_runtime.h>
#include <cuda_fp16.h>
#include <cstdint>
#include <cstddef>

// R2Ntab: B=131072, F=256, R=128, O=1
#define F_DIM 256
#define R_DIM 128
#define TILE_M 128
#define GRID_CTAS 148
#define NTHREADS 256

// ---------------- device scratch (no allocs allowed) ----------------
__device__ __align__(16) float  g_wexact[R_DIM * F_DIM]; // exact masked weights
__device__ __align__(16) __half g_wh[R_DIM * F_DIM];     // f16 masked weights [r][f]
__device__ float g_thresh[R_DIM];  // fires iff dot > thresh (inf if OR-gate off)
__device__ float g_bound[R_DIM];   // guaranteed |f16dot - exact| bound

// ---------------- helpers ----------------
static __device__ __forceinline__ uint32_t smem_u32(const void* p) {
    uint32_t a;
    asm("{ .reg .u64 t; cvta.to.shared.u64 t, %1; cvt.u32.u64 %0, t; }" : "=r"(a) : "l"(p));
    return a;
}

static __device__ __forceinline__ void ldmatrix_x4(uint32_t& r0, uint32_t& r1,
                                                   uint32_t& r2, uint32_t& r3,
                                                   uint32_t addr) {
    asm volatile("ldmatrix.sync.aligned.m8n8.x4.shared.b16 {%0,%1,%2,%3}, [%4];"
                 : "=r"(r0), "=r"(r1), "=r"(r2), "=r"(r3) : "r"(addr));
}

// f16-accumulate HMMA: D(2x half2) = A*B + D
static __device__ __forceinline__ void mma_f16(uint32_t* d, uint32_t a0, uint32_t a1,
                                               uint32_t a2, uint32_t a3,
                                               uint32_t b0, uint32_t b1) {
    asm volatile(
        "mma.sync.aligned.m16n8k16.row.col.f16.f16.f16.f16 "
        "{%0,%1}, {%2,%3,%4,%5}, {%6,%7}, {%0,%1};"
        : "+r"(d[0]), "+r"(d[1])
        : "r"(a0), "r"(a1), "r"(a2), "r"(a3), "r"(b0), "r"(b1));
}

// ---------------- SMEM layout ----------------
// A tiles (f16, swizzled): row stride 512B, 16B unit u' = u ^ (row&7)
static constexpr int A0_OFF   = 0;
static constexpr int A_BYTES  = TILE_M * F_DIM * 2;    // 65536
static constexpr int A1_OFF   = A0_OFF + A_BYTES;      // 65536
static constexpr int B_OFF    = A1_OFF + A_BYTES;      // 131072
static constexpr int B_BYTES  = R_DIM * F_DIM * 2;     // 65536
static constexpr int PART_OFF = B_OFF + B_BYTES;       // 196608  [2][128][2] ints
static constexpr int TH_OFF   = PART_OFF + 2 * TILE_M * 2 * 4;   // 198656
static constexpr int BND_OFF  = TH_OFF + R_DIM * 4;              // 199168
static constexpr int SMEM_TOTAL = BND_OFF + R_DIM * 4;           // 199680

// ---------------- precompute: mask, f16 weights, thresholds, bounds ----------------
__global__ void r2ntab_prep(const float* __restrict__ w_cancel,
                            const float* __restrict__ w_and,
                            const float* __restrict__ b_and,
                            const float* __restrict__ w_or) {
    __shared__ float s_relu[4], s_err[4], s_abs[4];
    const int r = blockIdx.x;
    const int t = threadIdx.x;          // 0..127
    float w0, w1;
    {
        int f0 = t, f1 = t + 128;
        w0 = (w_cancel[f0] < 0.0f) ? 0.0f : w_and[r * F_DIM + f0];
        w1 = (w_cancel[f1] < 0.0f) ? 0.0f : w_and[r * F_DIM + f1];
        g_wexact[r * F_DIM + f0] = w0;
        g_wexact[r * F_DIM + f1] = w1;
    }
    __half h0 = __float2half_rn(w0), h1 = __float2half_rn(w1);
    g_wh[r * F_DIM + t]       = h0;
    g_wh[r * F_DIM + t + 128] = h1;
    float relu = fmaxf(w0, 0.0f) + fmaxf(w1, 0.0f);
    float err  = fabsf(w0 - __half2float(h0)) + fabsf(w1 - __half2float(h1));
    float absh = fabsf(__half2float(h0)) + fabsf(__half2float(h1));
    #pragma unroll
    for (int s = 16; s > 0; s >>= 1) {
        relu += __shfl_xor_sync(0xffffffffu, relu, s);
        err  += __shfl_xor_sync(0xffffffffu, err, s);
        absh += __shfl_xor_sync(0xffffffffu, absh, s);
    }
    if ((t & 31) == 0) { s_relu[t >> 5] = relu; s_err[t >> 5] = err; s_abs[t >> 5] = absh; }
    __syncthreads();
    if (t == 0) {
        float rs = s_relu[0] + s_relu[1] + s_relu[2] + s_relu[3];
        float es = s_err[0] + s_err[1] + s_err[2] + s_err[3];
        float as = s_abs[0] + s_abs[1] + s_abs[2] + s_abs[3];
        if (w_or[r] > 0.0f) {
            g_thresh[r] = 0.999999f - b_and[r] + rs;
            g_bound[r]  = es + as * 0.02f + 2e-4f;   // f16 weight + accumulation slack
        } else {
            g_thresh[r] = __int_as_float(0x7f800000);  // +inf: never fires
            g_bound[r]  = 0.0f;
        }
    }
}

// ---------------- first-tile loader ----------------
static __device__ __forceinline__ void load_tile(const float* __restrict__ x,
                                                 int tile, char* __restrict__ abase,
                                                 int tid) {
    const float4* xp = reinterpret_cast<const float4*>(x) + (size_t)tile * TILE_M * (F_DIM / 4);
    #pragma unroll 8
    for (int i = tid; i < TILE_M * (F_DIM / 4); i += NTHREADS) {
        int row = i >> 6;
        int q   = i & 63;
        float4 v = xp[i];
        __half2 p0 = __floats2half2_rn(v.x, v.y);
        __half2 p1 = __floats2half2_rn(v.z, v.w);
        uint32_t u    = (uint32_t)(q >> 1);
        uint32_t off  = (uint32_t)row * 512u + ((u ^ (row & 7)) << 4) + ((q & 1) << 3);
        uint2 val;
        val.x = *reinterpret_cast<uint32_t*>(&p0);
        val.y = *reinterpret_cast<uint32_t*>(&p1);
        *reinterpret_cast<uint2*>(abase + off) = val;
    }
}

// exact fp32 recheck (guaranteed-correct slow path, ~0 hits/run)
static __device__ __noinline__ int exact_check(const float* __restrict__ x,
                                               int g_row, int rule) {
    const float4* xr = reinterpret_cast<const float4*>(x + (size_t)g_row * F_DIM);
    const float4* wr = reinterpret_cast<const float4*>(g_wexact + rule * F_DIM);
    float s = 0.0f;
    #pragma unroll 8
    for (int i = 0; i < F_DIM / 4; i++) {
        float4 a = xr[i], b = wr[i];
        s += a.x * b.x + a.y * b.y + a.z * b.z + a.w * b.w;
    }
    return s > g_thresh[rule] ? 1 : 0;
}

// ---------------- main persistent kernel: 256 threads, 8 warps, warp tile 32x64 ----
__global__ void __launch_bounds__(NTHREADS, 1)
r2ntab_main(const float* __restrict__ x, const float* __restrict__ b_or,
            float* __restrict__ out, int num_tiles) {
    extern __shared__ char smem[];
    const uint32_t sbase = smem_u32(smem);
    const int tid  = threadIdx.x;
    const int lane = tid & 31;
    const int wid  = tid >> 5;     // 0..7
    const int wm   = wid >> 1;     // 0..3 : M group (32 rows)
    const int wn   = wid & 1;      // 0..1 : N group (64 rules)

    // ---- stage B (f16 rules, 512B rows, swizzled) + tables, once ----
    {
        const uint4* wh4 = reinterpret_cast<const uint4*>(g_wh);
        #pragma unroll 4
        for (int i = tid; i < R_DIM * (F_DIM / 8); i += NTHREADS) {
            int r = i >> 5;
            int u = i & 31;
            uint4 v = wh4[i];
            uint32_t off = (uint32_t)r * 512u + (((uint32_t)u ^ (r & 7)) << 4);
            *reinterpret_cast<uint4*>(smem + B_OFF + off) = v;
        }
        if (tid < R_DIM) {
            reinterpret_cast<float*>(smem + TH_OFF)[tid]  = g_thresh[tid];
            reinterpret_cast<float*>(smem + BND_OFF)[tid] = g_bound[tid];
        }
    }
    const float bor0 = b_or[0];
    const float* th_s  = reinterpret_cast<const float*>(smem + TH_OFF);
    const float* bnd_s = reinterpret_cast<const float*>(smem + BND_OFF);
    const int rule_base = wn * 64 + (lane & 3) * 2;

    // ---- ldmatrix lane addresses ----
    const int idx = lane >> 3;
    const int s3  = lane & 7;
    uint32_t a_row[2];
    #pragma unroll
    for (int mt = 0; mt < 2; mt++)
        a_row[mt] = (uint32_t)(wm * 32 + mt * 16 + (idx & 1) * 8 + s3) * 512u;
    const uint32_t a_usel = (uint32_t)(idx >> 1);
    uint32_t b_row[8];
    #pragma unroll
    for (int nt = 0; nt < 8; nt++)
        b_row[nt] = sbase + B_OFF + (uint32_t)(wn * 64 + nt * 8 + s3) * 512u;
    const uint32_t b_usel = (uint32_t)(idx & 1);

    int* part = reinterpret_cast<int*>(smem + PART_OFF);   // [2][128][2]

    // loader invariants: i = tid + 256*j -> row = (tid>>6) + 4*j, q = tid&63
    const int q_l    = tid & 63;
    const int row0_l = tid >> 6;                 // 0..3
    const uint32_t u_l = (uint32_t)(q_l >> 1);
    // row&7 = row0_l + 4*(j&1): two swizzle constants by j parity
    uint32_t stc[2];
    #pragma unroll
    for (int p = 0; p < 2; p++)
        stc[p] = ((u_l ^ (uint32_t)(row0_l + 4 * p)) << 4) + ((uint32_t)(q_l & 1) << 3);

    const int t0 = blockIdx.x;
    int cur = 0;
    if (t0 < num_tiles) load_tile(x, t0, smem + A0_OFF, tid);
    __syncthreads();

    int it = 0;
    for (int t = t0; t < num_tiles; t += GRID_CTAS, it++) {
        const int tn = t + GRID_CTAS;
        const bool has_next = (tn < num_tiles);
        const float4* xn = reinterpret_cast<const float4*>(x) +
                           (size_t)tn * TILE_M * (F_DIM / 4);
        char* nbuf = smem + (cur ? A0_OFF : A1_OFF);

        // gmem loader: 4 groups of 8 float4/thread; 2 groups (16 LDG.128) in flight
        float4 buf[2][8];
        if (has_next) {
            #pragma unroll
            for (int jj = 0; jj < 8; jj++) buf[0][jj] = xn[tid + NTHREADS * jj];
            #pragma unroll
            for (int jj = 0; jj < 8; jj++) buf[1][jj] = xn[tid + NTHREADS * (8 + jj)];
        }

        const uint32_t abuf = sbase + (cur ? A1_OFF : A0_OFF);
        uint32_t acc[2][8][2];
        #pragma unroll
        for (int mt = 0; mt < 2; mt++)
            #pragma unroll
            for (int nt = 0; nt < 8; nt++) { acc[mt][nt][0] = 0u; acc[mt][nt][1] = 0u; }

        // ---- k-loop: 6 LDSM + 16 HMMA per kt, loader drains every 4th kt ----
        #pragma unroll
        for (int kt = 0; kt < 16; kt++) {
            uint32_t bf[8][2];
            #pragma unroll
            for (int p = 0; p < 4; p++) {
                uint32_t addr = b_row[2 * p + (idx >> 1)] +
                                ((((uint32_t)(2 * kt) + b_usel) ^ s3) << 4);
                ldmatrix_x4(bf[2 * p][0], bf[2 * p][1],
                            bf[2 * p + 1][0], bf[2 * p + 1][1], addr);
            }
            #pragma unroll
            for (int mt = 0; mt < 2; mt++) {
                uint32_t a0, a1, a2, a3;
                uint32_t addr = abuf + a_row[mt] +
                                ((((uint32_t)(2 * kt) + a_usel) ^ s3) << 4);
                ldmatrix_x4(a0, a1, a2, a3, addr);
                #pragma unroll
                for (int nt = 0; nt < 8; nt++)
                    mma_f16(acc[mt][nt], a0, a1, a2, a3, bf[nt][0], bf[nt][1]);
            }

            // every 4th kt: drain arrived group g, issue group g+2
            if ((kt & 3) == 3 && has_next) {
                const int g = kt >> 2;            // 0..3
                #pragma unroll
                for (int jj = 0; jj < 8; jj++) {
                    const int j   = g * 8 + jj;
                    const int row = row0_l + 4 * j;
                    float4 v = buf[g & 1][jj];
                    __half2 p0 = __floats2half2_rn(v.x, v.y);
                    __half2 p1 = __floats2half2_rn(v.z, v.w);
                    uint2 val;
                    val.x = *reinterpret_cast<uint32_t*>(&p0);
                    val.y = *reinterpret_cast<uint32_t*>(&p1);
                    *reinterpret_cast<uint2*>(nbuf + (uint32_t)row * 512u + stc[jj & 1]) = val;
                }
                if (g < 2) {
                    #pragma unroll
                    for (int jj = 0; jj < 8; jj++)
                        buf[g & 1][jj] = xn[tid + NTHREADS * ((g + 2) * 8 + jj)];
                }
            }
        }

        // ---- epilogue: threshold-count with exact-recheck guard ----
        const int par = it & 1;
        #pragma unroll
        for (int mt = 0; mt < 2; mt++) {
            int rA = wm * 32 + mt * 16 + (lane >> 2);
            int rB = rA + 8;
            int cA = 0, cB = 0;
            #pragma unroll
            for (int nt = 0; nt < 8; nt++) {
                float2 lo = __half22float2(*reinterpret_cast<__half2*>(&acc[mt][nt][0]));
                float2 hi = __half22float2(*reinterpret_cast<__half2*>(&acc[mt][nt][1]));
                #pragma unroll
                for (int c = 0; c < 2; c++) {
                    const int rule = rule_base + nt * 8 + c;
                    const float thv  = th_s[rule];
                    const float bndv = bnd_s[rule];
                    float dA = (c ? lo.y : lo.x) - thv;
                    float dB = (c ? hi.y : hi.x) - thv;
                    if (fabsf(dA) <= bndv)
                        cA += exact_check(x, t * TILE_M + rA, rule);
                    else
                        cA += (dA > 0.0f) ? 1 : 0;
                    if (fabsf(dB) <= bndv)
                        cB += exact_check(x, t * TILE_M + rB, rule);
                    else
                        cB += (dB > 0.0f) ? 1 : 0;
                }
            }
            cA += __shfl_xor_sync(0xffffffffu, cA, 1);
            cA += __shfl_xor_sync(0xffffffffu, cA, 2);
            cB += __shfl_xor_sync(0xffffffffu, cB, 1);
            cB += __shfl_xor_sync(0xffffffffu, cB, 2);
            if ((lane & 3) == 0) {
                part[par * 256 + rA * 2 + wn] = cA;
                part[par * 256 + rB * 2 + wn] = cB;
            }
        }
        __syncthreads();   // partials ready; next-tile STS complete

        if (tid < TILE_M) {
            int2 qv = *reinterpret_cast<int2*>(&part[par * 256 + tid * 2]);
            out[t * TILE_M + tid] = (float)(qv.x + qv.y) + bor0;
        }
        cur ^= 1;
        // part parity ping-pong: slot `par` not rewritten until 2 barriers later.
    }
}

extern "C" void kernel_launch(void* const* d_in, const int* in_sizes, int n_in,
                              void* d_out, int out_size) {
    const float* x        = (const float*)d_in[0];
    const float* w_cancel = (const float*)d_in[1];
    const float* w_and    = (const float*)d_in[2];
    const float* b_and    = (const float*)d_in[3];
    const float* w_or     = (const float*)d_in[4];
    const float* b_or     = (const float*)d_in[5];
    float* out = (float*)d_out;

    const int B_total   = in_sizes[0] / F_DIM;   // 131072
    const int num_tiles = B_total / TILE_M;      // 1024

    cudaFuncSetAttribute(r2ntab_main, cudaFuncAttributeMaxDynamicSharedMemorySize, SMEM_TOTAL);

    r2ntab_prep<<<R_DIM, 128>>>(w_cancel, w_and, b_and, w_or);
    r2ntab_main<<<GRID_CTAS, NTHREADS, SMEM_TOTAL>>>(x, b_or, out, num_tiles);
    (void)n_in; (void)out_size;
}